// round 14
// baseline (speedup 1.0000x reference)
#include <cuda_runtime.h>
#include <cstdint>
#include <cstddef>

// Problem constants
constexpr int B_  = 64;
constexpr int T_  = 512;
constexpr int D_  = 300;
constexpr int H_  = 256;
constexpr int G_  = 1024;   // 4*H
constexpr int C_  = 9;
constexpr int NTOK = B_ * T_;          // 32768
constexpr int NC_DIR = 64;             // CTAs per direction in recurrence
constexpr int RTHREADS = 512;

// Output layout: logits [B,T,C], log_likelihood [B], trans [C,C]
constexpr int OFF_LL = NTOK * C_;      // 294912
constexpr int OFF_TR = OFF_LL + B_;    // 294976

// ---------------- scratch (device globals; no cudaMalloc allowed) -----------
__device__ float g_xz[2][NTOK][G_];          // 256 MB: emb@Wk + b, both dirs
__device__ float g_hs[2][B_][T_][H_];        // 64 MB: LSTM hidden outputs
__device__ unsigned g_bar[2];                // grid barrier counters

// ---------------- kernel 0: reset barrier counters --------------------------
__global__ void bilstm_init_kernel() {
    if (threadIdx.x < 2) g_bar[threadIdx.x] = 0u;
}

// ---------------- kernel 1: fused embedding gather + input GEMM -------------
// g_xz[dir][m][n] = sum_k emb[tok[m]][k] * Wk[k][n] + bias[n]
// tiles 64(M) x 64(N) x 16(K), 256 threads, 4x4 register tile per thread.
__global__ void __launch_bounds__(256)
bilstm_xz_gemm_kernel(const int* __restrict__ inputs,
                      const float* __restrict__ emb,
                      const float* __restrict__ Wk_f, const float* __restrict__ b_f,
                      const float* __restrict__ Wk_b, const float* __restrict__ b_b)
{
    __shared__ __align__(16) float As[16 * 68];   // [k][m], padded
    __shared__ __align__(16) float Bs[16 * 68];   // [k][n], padded

    const int dir = blockIdx.z;
    const float* Wk   = dir ? Wk_b : Wk_f;
    const float* bias = dir ? b_b  : b_f;
    const int n0 = blockIdx.x * 64;
    const int m0 = blockIdx.y * 64;
    const int tid = threadIdx.x;

    const int lm = tid >> 2, kq = tid & 3;    // A-load mapping
    const int kr = tid >> 4, nq = tid & 15;   // B-load mapping
    const int mt = tid >> 4, nt = tid & 15;   // compute mapping

    const int tok = inputs[m0 + lm];
    const float* arow = emb + (size_t)tok * D_;

    float acc[4][4];
#pragma unroll
    for (int u = 0; u < 4; u++)
#pragma unroll
        for (int v = 0; v < 4; v++) acc[u][v] = 0.f;

    for (int k0 = 0; k0 < 304; k0 += 16) {
        // ---- load A tile (gathered embedding rows), transposed to [k][m]
        {
            int kk = k0 + kq * 4;
            if (kk + 3 < D_) {
                float4 v = *(const float4*)(arow + kk);
                As[(kq*4+0)*68 + lm] = v.x;
                As[(kq*4+1)*68 + lm] = v.y;
                As[(kq*4+2)*68 + lm] = v.z;
                As[(kq*4+3)*68 + lm] = v.w;
            } else {
#pragma unroll
                for (int e = 0; e < 4; e++)
                    As[(kq*4+e)*68 + lm] = (kk + e < D_) ? arow[kk + e] : 0.f;
            }
        }
        // ---- load B tile [k][n]
        {
            int kk = k0 + kr;
            float4 v = make_float4(0.f, 0.f, 0.f, 0.f);
            if (kk < D_) v = *(const float4*)(Wk + (size_t)kk * G_ + n0 + nq * 4);
            *(float4*)(Bs + kr*68 + nq*4) = v;
        }
        __syncthreads();
#pragma unroll
        for (int k = 0; k < 16; k++) {
            float4 a  = *(const float4*)(As + k*68 + mt*4);
            float4 bb = *(const float4*)(Bs + k*68 + nt*4);
            acc[0][0] += a.x*bb.x; acc[0][1] += a.x*bb.y; acc[0][2] += a.x*bb.z; acc[0][3] += a.x*bb.w;
            acc[1][0] += a.y*bb.x; acc[1][1] += a.y*bb.y; acc[1][2] += a.y*bb.z; acc[1][3] += a.y*bb.w;
            acc[2][0] += a.z*bb.x; acc[2][1] += a.z*bb.y; acc[2][2] += a.z*bb.z; acc[2][3] += a.z*bb.w;
            acc[3][0] += a.w*bb.x; acc[3][1] += a.w*bb.y; acc[3][2] += a.w*bb.z; acc[3][3] += a.w*bb.w;
        }
        __syncthreads();
    }

    float* outp = &g_xz[dir][0][0];
    const int n = n0 + nt * 4;
    float4 bv = *(const float4*)(bias + n);
#pragma unroll
    for (int u = 0; u < 4; u++) {
        int m = m0 + mt * 4 + u;
        float4 r;
        r.x = acc[u][0] + bv.x; r.y = acc[u][1] + bv.y;
        r.z = acc[u][2] + bv.z; r.w = acc[u][3] + bv.w;
        *(float4*)(outp + (size_t)m * G_ + n) = r;
    }
}

// ---------------- kernel 2: persistent bidirectional LSTM recurrence --------
// Grid: 128 CTAs (blocks 0..63 forward, 64..127 backward), 512 threads each.
// CTA (dir, j) owns hidden cols [4j, 4j+4) for all 64 batches.
// Per step: z = h_prev @ Wr_slice (smem, shuffle-reduced 8-way K-split),
// gates, state update, write hs[tt], grid barrier per direction.
__global__ void __launch_bounds__(RTHREADS, 1)
bilstm_lstm_kernel(const float* __restrict__ Wr_f,
                   const float* __restrict__ Wr_b,
                   const int* __restrict__ lengths)
{
    extern __shared__ __align__(16) float smem[];
    float* Wr_s = smem;                // 256*20 = 5120 floats (pad 20, f4-aligned rows)
    float* h_s  = Wr_s + 5120;         // 64*257 = 16448 floats ([b][k], pad 257)
    float* z_s  = h_s + 16448;         // 64*17  = 1088 floats
    float* c_s  = z_s + 1088;          // 256 floats
    int*   len_s = (int*)(c_s + 256);  // 64 ints

    const int tid = threadIdx.x;
    const int dir = blockIdx.x >> 6;
    const int j   = blockIdx.x & 63;
    const float* Wr  = dir ? Wr_b : Wr_f;
    const float* xzp = &g_xz[dir][0][0];
    float* hsp = &g_hs[dir][0][0][0];

    // prologue: Wr slice -> smem, zero state
    for (int idx = tid; idx < 4096; idx += RTHREADS) {
        int k = idx >> 4, gi = idx & 15;
        int gate = gi >> 2, cc = gi & 3;
        Wr_s[k*20 + gi] = Wr[(size_t)k * G_ + gate * H_ + j*4 + cc];
    }
    for (int idx = tid; idx < 64*257; idx += RTHREADS) h_s[idx] = 0.f;
    if (tid < 256) c_s[tid] = 0.f;
    if (tid < 64)  len_s[tid] = lengths[tid];
    __syncthreads();

    const int kg = tid & 7;
    const int og = tid >> 3;
    const int b0 = (og >> 2) * 4;      // == 4*warp_id: broadcast within warp
    const int gate = og & 3;

    const float*  hp0 = h_s + (b0+0)*257 + kg;
    const float*  hp1 = h_s + (b0+1)*257 + kg;
    const float*  hp2 = h_s + (b0+2)*257 + kg;
    const float*  hp3 = h_s + (b0+3)*257 + kg;
    const float4* wp  = (const float4*)Wr_s + kg*5 + gate;

    const int gb = tid >> 2, gc = tid & 3;     // gate-phase mapping (tid<256)
    const int hc = j*4 + gc;

    volatile unsigned* barp = (volatile unsigned*)&g_bar[dir];

    for (int s = 0; s < T_; s++) {
        const int tt = dir ? (T_ - 1 - s) : s;

        // prefetch xz for this step (hides DRAM latency behind the GEMV)
        float xz0 = 0.f, xz1 = 0.f, xz2 = 0.f, xz3 = 0.f;
        if (tid < 256) {
            const float* xb = xzp + (size_t)(gb * T_ + tt) * G_ + hc;
            xz0 = xb[0]; xz1 = xb[H_]; xz2 = xb[2*H_]; xz3 = xb[3*H_];
        }

        // ---- z = h_prev @ Wr_slice  (8-way K split over kg lanes)
        float acc[4][4];
#pragma unroll
        for (int u = 0; u < 4; u++)
#pragma unroll
            for (int v = 0; v < 4; v++) acc[u][v] = 0.f;

#pragma unroll 4
        for (int i = 0; i < 32; i++) {
            float4 w = wp[i * 40];             // k = i*8 + kg
            float h0v = hp0[i * 8];
            float h1v = hp1[i * 8];
            float h2v = hp2[i * 8];
            float h3v = hp3[i * 8];
            acc[0][0] += h0v*w.x; acc[0][1] += h0v*w.y; acc[0][2] += h0v*w.z; acc[0][3] += h0v*w.w;
            acc[1][0] += h1v*w.x; acc[1][1] += h1v*w.y; acc[1][2] += h1v*w.z; acc[1][3] += h1v*w.w;
            acc[2][0] += h2v*w.x; acc[2][1] += h2v*w.y; acc[2][2] += h2v*w.z; acc[2][3] += h2v*w.w;
            acc[3][0] += h3v*w.x; acc[3][1] += h3v*w.y; acc[3][2] += h3v*w.z; acc[3][3] += h3v*w.w;
        }
        // reduce partials across the 8 kg lanes (low 3 bits of lane id)
#pragma unroll
        for (int u = 0; u < 4; u++)
#pragma unroll
            for (int v = 0; v < 4; v++) {
                float a = acc[u][v];
                a += __shfl_down_sync(0xffffffffu, a, 4);
                a += __shfl_down_sync(0xffffffffu, a, 2);
                a += __shfl_down_sync(0xffffffffu, a, 1);
                acc[u][v] = a;
            }
        if (kg == 0) {
#pragma unroll
            for (int u = 0; u < 4; u++)
#pragma unroll
                for (int v = 0; v < 4; v++)
                    z_s[(b0+u)*17 + gate*4 + v] = acc[u][v];
        }
        __syncthreads();

        // ---- gate phase (tid < 256: one thread per (batch, owned col))
        if (tid < 256) {
            float zi = z_s[gb*17 + 0  + gc] + xz0;
            float zf = z_s[gb*17 + 4  + gc] + xz1;
            float zg = z_s[gb*17 + 8  + gc] + xz2;
            float zo = z_s[gb*17 + 12 + gc] + xz3;
            float ig = 1.f / (1.f + expf(-zi));
            float fg = 1.f / (1.f + expf(-zf));
            float gg = tanhf(zg);
            float og_ = 1.f / (1.f + expf(-zo));
            float cold = c_s[tid];
            float cn = fg * cold + ig * gg;
            float hn = og_ * tanhf(cn);
            bool mv = (tt < len_s[gb]);
            float hout = mv ? hn : h_s[gb*257 + hc];
            if (mv) c_s[tid] = cn;
            hsp[(size_t)(gb * T_ + tt) * H_ + hc] = hout;
            __threadfence();   // release this thread's hs write to GPU scope
        }
        __syncthreads();

        // ---- grid barrier for this direction (monotonic counter)
        if (tid == 0) {
            atomicAdd((unsigned*)&g_bar[dir], 1u);
            unsigned target = (unsigned)(s + 1) * NC_DIR;
            while (*barp < target) __nanosleep(64);
            __threadfence();
        }
        __syncthreads();

        // ---- load h for next step: hs[:, tt, :] -> h_s[b][k]
        if (s < T_ - 1) {
            int lb = tid >> 3, kp = tid & 7;
            const float4* src = (const float4*)(hsp + (size_t)(lb * T_ + tt) * H_);
            float* dst = h_s + lb * 257;
#pragma unroll
            for (int ii = 0; ii < 8; ii++) {
                float4 v = src[ii * 8 + kp];   // k = 32*ii + 4*kp
                int kb = ii * 32 + kp * 4;
                dst[kb + 0] = v.x; dst[kb + 1] = v.y;
                dst[kb + 2] = v.z; dst[kb + 3] = v.w;
            }
            __syncthreads();
        }
    }
}

// ---------------- kernel 3: dense projection to logits -----------------------
// logits[tok][c] = concat(h_f,h_b)[tok] . dense_W[:,c] + dense_b[c]
constexpr int DTOK = 16;
__global__ void __launch_bounds__(160)
bilstm_dense_kernel(const float* __restrict__ W, const float* __restrict__ bias,
                    float* __restrict__ out)
{
    __shared__ __align__(16) float hsm[DTOK * 513];
    const int tid = threadIdx.x;
    const int tok0 = blockIdx.x * DTOK;

    for (int idx = tid; idx < DTOK * 512; idx += 160) {
        int tk = idx >> 9, k = idx & 511;
        int tg = tok0 + tk;
        int b = tg >> 9, t = tg & 511;
        float v = (k < H_) ? g_hs[0][b][t][k] : g_hs[1][b][t][k - H_];
        hsm[tk * 513 + k] = v;
    }
    __syncthreads();

    if (tid < DTOK * C_) {
        int tk = tid / C_, c = tid % C_;
        float acc = bias[c];
        const float* hr = hsm + tk * 513;
#pragma unroll 8
        for (int k = 0; k < 512; k++) acc += hr[k] * W[k * C_ + c];
        out[(size_t)(tok0 + tk) * C_ + c] = acc;
    }
}

// ---------------- kernel 4: CRF log-likelihood + trans copy -----------------
__global__ void __launch_bounds__(32)
bilstm_crf_kernel(const float* __restrict__ logits,
                  const int* __restrict__ targets,
                  const int* __restrict__ lengths,
                  const float* __restrict__ trans,
                  float* __restrict__ out_ll, float* __restrict__ out_trans)
{
    __shared__ float tr[81];
    __shared__ float alpha[16];
    const int b = blockIdx.x;
    const int lane = threadIdx.x;

    for (int i = lane; i < 81; i += 32) tr[i] = trans[i];
    if (b == 0)
        for (int i = lane; i < 81; i += 32) out_trans[i] = trans[i];
    __syncwarp();

    const int len = lengths[b];
    const float* lg = logits + (size_t)b * T_ * C_;
    const int* tg = targets + b * T_;

    // unary + binary sums
    float us = 0.f, bs = 0.f;
    for (int t = lane; t < T_; t += 32) {
        if (t < len)     us += lg[t * C_ + tg[t]];
        if (t < len - 1) bs += tr[tg[t] * C_ + tg[t + 1]];
    }
#pragma unroll
    for (int off = 16; off; off >>= 1) {
        us += __shfl_xor_sync(0xffffffffu, us, off);
        bs += __shfl_xor_sync(0xffffffffu, bs, off);
    }

    // forward algorithm
    if (lane < C_) alpha[lane] = lg[lane];
    __syncwarp();
    for (int t = 1; t < len; t++) {
        float a_new = 0.f;
        if (lane < C_) {
            float v[C_];
            float m = -1e30f;
#pragma unroll
            for (int c = 0; c < C_; c++) {
                v[c] = alpha[c] + tr[c * C_ + lane];
                m = fmaxf(m, v[c]);
            }
            float ssum = 0.f;
#pragma unroll
            for (int c = 0; c < C_; c++) ssum += expf(v[c] - m);
            a_new = m + logf(ssum) + lg[t * C_ + lane];
        }
        __syncwarp();
        if (lane < C_) alpha[lane] = a_new;
        __syncwarp();
    }

    if (lane == 0) {
        float m = -1e30f;
        for (int c = 0; c < C_; c++) m = fmaxf(m, alpha[c]);
        float ssum = 0.f;
        for (int c = 0; c < C_; c++) ssum += expf(alpha[c] - m);
        out_ll[b] = us + bs - (m + logf(ssum));
    }
}

// ---------------- launch ------------------------------------------------------
extern "C" void kernel_launch(void* const* d_in, const int* in_sizes, int n_in,
                              void* d_out, int out_size) {
    (void)in_sizes; (void)n_in; (void)out_size;
    const int*   inputs  = (const int*)  d_in[0];
    const int*   lengths = (const int*)  d_in[1];
    const int*   targets = (const int*)  d_in[2];
    const float* emb     = (const float*)d_in[3];
    const float* Wk_f    = (const float*)d_in[4];
    const float* Wr_f    = (const float*)d_in[5];
    const float* b_f     = (const float*)d_in[6];
    const float* Wk_b    = (const float*)d_in[7];
    const float* Wr_b    = (const float*)d_in[8];
    const float* b_b     = (const float*)d_in[9];
    const float* dW      = (const float*)d_in[10];
    const float* db      = (const float*)d_in[11];
    const float* trans   = (const float*)d_in[12];
    float* out = (float*)d_out;

    // dynamic smem for the persistent LSTM kernel (~90 KB)
    const int lstm_smem = (5120 + 16448 + 1088 + 256) * 4 + 64 * 4;  // 91904 B
    cudaFuncSetAttribute(bilstm_lstm_kernel,
                         cudaFuncAttributeMaxDynamicSharedMemorySize, lstm_smem);

    bilstm_init_kernel<<<1, 32>>>();

    dim3 gA(G_ / 64, NTOK / 64, 2);   // 16 x 512 x 2
    bilstm_xz_gemm_kernel<<<gA, 256>>>(inputs, emb, Wk_f, b_f, Wk_b, b_b);

    bilstm_lstm_kernel<<<2 * NC_DIR, RTHREADS, lstm_smem>>>(Wr_f, Wr_b, lengths);

    bilstm_dense_kernel<<<NTOK / DTOK, 160>>>(dW, db, out);

    bilstm_crf_kernel<<<B_, 32>>>(out, targets, lengths, trans,
                                  out + OFF_LL, out + OFF_TR);
}

// round 15
// speedup vs baseline: 1.1649x; 1.1649x over previous
#include <cuda_runtime.h>
#include <cstdint>
#include <cstddef>

// Problem constants
constexpr int B_  = 64;
constexpr int T_  = 512;
constexpr int D_  = 300;
constexpr int H_  = 256;
constexpr int G_  = 1024;   // 4*H
constexpr int C_  = 9;
constexpr int NTOK = B_ * T_;          // 32768
constexpr int NC_DIR = 64;             // CTAs per direction in recurrence
constexpr int RTHREADS = 512;

// Output layout: logits [B,T,C], log_likelihood [B], trans [C,C]
constexpr int OFF_LL = NTOK * C_;      // 294912
constexpr int OFF_TR = OFF_LL + B_;    // 294976

// ---------------- scratch (device globals; no cudaMalloc allowed) -----------
__device__ float g_xz[2][NTOK][G_];          // 256 MB: emb@Wk + b, both dirs
__device__ float g_hs[2][B_][T_][H_];        // 64 MB: LSTM hidden outputs
__device__ unsigned g_bar[2];                // grid barrier counters

// ---------------- kernel 0: reset barrier counters --------------------------
__global__ void bilstm_init_kernel() {
    if (threadIdx.x < 2) g_bar[threadIdx.x] = 0u;
}

// ---------------- tf32 mma helpers ------------------------------------------
__device__ __forceinline__ unsigned f2tf(float f) {
    unsigned u;
    asm("cvt.rna.tf32.f32 %0, %1;" : "=r"(u) : "f"(f));
    return u;
}
__device__ __forceinline__ void mma_tf32(float c[4], const unsigned a[4], const unsigned b[2]) {
    asm volatile(
        "mma.sync.aligned.m16n8k8.row.col.f32.tf32.tf32.f32 "
        "{%0,%1,%2,%3}, {%4,%5,%6,%7}, {%8,%9}, {%0,%1,%2,%3};"
        : "+f"(c[0]), "+f"(c[1]), "+f"(c[2]), "+f"(c[3])
        : "r"(a[0]), "r"(a[1]), "r"(a[2]), "r"(a[3]), "r"(b[0]), "r"(b[1]));
}

// ---------------- kernel 1: fused embedding gather + input GEMM (tf32 HMMA) --
// g_xz[dir][m][n] = sum_k emb[tok[m]][k] * Wk[k][n] + bias[n]
// Tile 64(M) x 64(N) x 16(K). 128 threads = 4 warps, warp tile 32x32.
// Fully-masked 64-token m-tiles are skipped (LSTM discards those xz values).
__global__ void __launch_bounds__(128)
bilstm_xz_gemm_kernel(const int* __restrict__ inputs,
                      const int* __restrict__ lengths,
                      const float* __restrict__ emb,
                      const float* __restrict__ Wk_f, const float* __restrict__ b_f,
                      const float* __restrict__ Wk_b, const float* __restrict__ b_b)
{
    __shared__ __align__(16) float As[64 * 20];   // [m][k], stride 20 (conflict-free frags)
    __shared__ __align__(16) float Bs[16 * 72];   // [k][n], stride 72 (conflict-free frags)

    const int m0 = blockIdx.y * 64;
    // skip tiles where every token is masked (t >= length): values never used
    {
        const int bb = m0 >> 9;
        const int t0 = m0 & 511;
        if (t0 >= lengths[bb]) return;
    }

    const int dir = blockIdx.z;
    const float* Wk   = dir ? Wk_b : Wk_f;
    const float* bias = dir ? b_b  : b_f;
    const int n0 = blockIdx.x * 64;
    const int tid  = threadIdx.x;
    const int lane = tid & 31;
    const int wid  = tid >> 5;

    // loader mappings
    const int lm = tid >> 1, kq = (tid & 1) * 8;           // A: 64 rows x (2 x 8k)
    const int kr = tid >> 3, nq = (tid & 7) * 8;           // B: 16 rows x (8 x 8n)
    // compute mapping
    const int mw = (wid & 1) * 32, nw = (wid >> 1) * 32;   // warp tile origin
    const int g = lane >> 2, q = lane & 3;

    const int tok = inputs[m0 + lm];
    const float* arow = emb + (size_t)tok * D_;

    float acc[2][4][4];
#pragma unroll
    for (int mi = 0; mi < 2; mi++)
#pragma unroll
        for (int ni = 0; ni < 4; ni++)
#pragma unroll
            for (int e = 0; e < 4; e++) acc[mi][ni][e] = 0.f;

    for (int k0 = 0; k0 < 304; k0 += 16) {
        const bool full = (k0 + 16 <= D_);
        // ---- A tile: gathered embedding rows -> As[m][k]
        {
            float* dst = As + lm * 20 + kq;
            const int kk = k0 + kq;
            if (full) {
                float4 v0 = *(const float4*)(arow + kk);
                float4 v1 = *(const float4*)(arow + kk + 4);
                *(float4*)(dst)     = v0;
                *(float4*)(dst + 4) = v1;
            } else {
#pragma unroll
                for (int e = 0; e < 8; e++)
                    dst[e] = (kk + e < D_) ? arow[kk + e] : 0.f;
            }
        }
        // ---- B tile: Wk -> Bs[k][n]
        {
            float* dst = Bs + kr * 72 + nq;
            const float* src = Wk + (size_t)(k0 + kr) * G_ + n0 + nq;
            if (full || (k0 + kr < D_)) {
                *(float4*)(dst)     = *(const float4*)(src);
                *(float4*)(dst + 4) = *(const float4*)(src + 4);
            } else {
                *(float4*)(dst)     = make_float4(0.f, 0.f, 0.f, 0.f);
                *(float4*)(dst + 4) = make_float4(0.f, 0.f, 0.f, 0.f);
            }
        }
        __syncthreads();

#pragma unroll
        for (int kb = 0; kb < 16; kb += 8) {
            unsigned af[2][4], bf[4][2];
#pragma unroll
            for (int mi = 0; mi < 2; mi++) {
                const float* ap = As + (mw + mi * 16 + g) * 20 + kb + q;
                af[mi][0] = f2tf(ap[0]);
                af[mi][1] = f2tf(ap[8 * 20]);
                af[mi][2] = f2tf(ap[4]);
                af[mi][3] = f2tf(ap[8 * 20 + 4]);
            }
#pragma unroll
            for (int ni = 0; ni < 4; ni++) {
                const float* bp = Bs + (kb + q) * 72 + nw + ni * 8 + g;
                bf[ni][0] = f2tf(bp[0]);
                bf[ni][1] = f2tf(bp[4 * 72]);
            }
#pragma unroll
            for (int mi = 0; mi < 2; mi++)
#pragma unroll
                for (int ni = 0; ni < 4; ni++)
                    mma_tf32(acc[mi][ni], af[mi], bf[ni]);
        }
        __syncthreads();
    }

    // ---- epilogue: +bias, store
    float* outp = &g_xz[dir][0][0];
#pragma unroll
    for (int mi = 0; mi < 2; mi++) {
        const int r = m0 + mw + mi * 16 + g;
#pragma unroll
        for (int ni = 0; ni < 4; ni++) {
            const int cc = n0 + nw + ni * 8 + q * 2;
            float2 bv = *(const float2*)(bias + cc);
            float2 o0, o1;
            o0.x = acc[mi][ni][0] + bv.x; o0.y = acc[mi][ni][1] + bv.y;
            o1.x = acc[mi][ni][2] + bv.x; o1.y = acc[mi][ni][3] + bv.y;
            *(float2*)(outp + (size_t)r * G_ + cc)       = o0;
            *(float2*)(outp + (size_t)(r + 8) * G_ + cc) = o1;
        }
    }
}

// ---------------- kernel 2: persistent bidirectional LSTM recurrence --------
// Grid: 128 CTAs (blocks 0..63 forward, 64..127 backward), 512 threads each.
// CTA (dir, j) owns hidden cols [4j, 4j+4) for all 64 batches.
__global__ void __launch_bounds__(RTHREADS, 1)
bilstm_lstm_kernel(const float* __restrict__ Wr_f,
                   const float* __restrict__ Wr_b,
                   const int* __restrict__ lengths)
{
    extern __shared__ __align__(16) float smem[];
    float* Wr_s = smem;                // 256*20 = 5120 floats
    float* h_s  = Wr_s + 5120;         // 64*257 = 16448 floats ([b][k], pad 257)
    float* z_s  = h_s + 16448;         // 64*17  = 1088 floats
    float* c_s  = z_s + 1088;          // 256 floats
    int*   len_s = (int*)(c_s + 256);  // 64 ints

    const int tid = threadIdx.x;
    const int dir = blockIdx.x >> 6;
    const int j   = blockIdx.x & 63;
    const float* Wr  = dir ? Wr_b : Wr_f;
    const float* xzp = &g_xz[dir][0][0];
    float* hsp = &g_hs[dir][0][0][0];

    for (int idx = tid; idx < 4096; idx += RTHREADS) {
        int k = idx >> 4, gi = idx & 15;
        int gate = gi >> 2, cc = gi & 3;
        Wr_s[k*20 + gi] = Wr[(size_t)k * G_ + gate * H_ + j*4 + cc];
    }
    for (int idx = tid; idx < 64*257; idx += RTHREADS) h_s[idx] = 0.f;
    if (tid < 256) c_s[tid] = 0.f;
    if (tid < 64)  len_s[tid] = lengths[tid];
    __syncthreads();

    const int kg = tid & 7;
    const int og = tid >> 3;
    const int b0 = (og >> 2) * 4;
    const int gate = og & 3;

    const float*  hp0 = h_s + (b0+0)*257 + kg;
    const float*  hp1 = h_s + (b0+1)*257 + kg;
    const float*  hp2 = h_s + (b0+2)*257 + kg;
    const float*  hp3 = h_s + (b0+3)*257 + kg;
    const float4* wp  = (const float4*)Wr_s + kg*5 + gate;

    const int gb = tid >> 2, gc = tid & 3;
    const int hc = j*4 + gc;

    volatile unsigned* barp = (volatile unsigned*)&g_bar[dir];

    for (int s = 0; s < T_; s++) {
        const int tt = dir ? (T_ - 1 - s) : s;

        float xz0 = 0.f, xz1 = 0.f, xz2 = 0.f, xz3 = 0.f;
        if (tid < 256) {
            const float* xb = xzp + (size_t)(gb * T_ + tt) * G_ + hc;
            xz0 = xb[0]; xz1 = xb[H_]; xz2 = xb[2*H_]; xz3 = xb[3*H_];
        }

        float acc[4][4];
#pragma unroll
        for (int u = 0; u < 4; u++)
#pragma unroll
            for (int v = 0; v < 4; v++) acc[u][v] = 0.f;

#pragma unroll 4
        for (int i = 0; i < 32; i++) {
            float4 w = wp[i * 40];
            float h0v = hp0[i * 8];
            float h1v = hp1[i * 8];
            float h2v = hp2[i * 8];
            float h3v = hp3[i * 8];
            acc[0][0] += h0v*w.x; acc[0][1] += h0v*w.y; acc[0][2] += h0v*w.z; acc[0][3] += h0v*w.w;
            acc[1][0] += h1v*w.x; acc[1][1] += h1v*w.y; acc[1][2] += h1v*w.z; acc[1][3] += h1v*w.w;
            acc[2][0] += h2v*w.x; acc[2][1] += h2v*w.y; acc[2][2] += h2v*w.z; acc[2][3] += h2v*w.w;
            acc[3][0] += h3v*w.x; acc[3][1] += h3v*w.y; acc[3][2] += h3v*w.z; acc[3][3] += h3v*w.w;
        }
#pragma unroll
        for (int u = 0; u < 4; u++)
#pragma unroll
            for (int v = 0; v < 4; v++) {
                float a = acc[u][v];
                a += __shfl_down_sync(0xffffffffu, a, 4);
                a += __shfl_down_sync(0xffffffffu, a, 2);
                a += __shfl_down_sync(0xffffffffu, a, 1);
                acc[u][v] = a;
            }
        if (kg == 0) {
#pragma unroll
            for (int u = 0; u < 4; u++)
#pragma unroll
                for (int v = 0; v < 4; v++)
                    z_s[(b0+u)*17 + gate*4 + v] = acc[u][v];
        }
        __syncthreads();

        if (tid < 256) {
            float zi = z_s[gb*17 + 0  + gc] + xz0;
            float zf = z_s[gb*17 + 4  + gc] + xz1;
            float zg = z_s[gb*17 + 8  + gc] + xz2;
            float zo = z_s[gb*17 + 12 + gc] + xz3;
            float ig = 1.f / (1.f + expf(-zi));
            float fg = 1.f / (1.f + expf(-zf));
            float gg = tanhf(zg);
            float og_ = 1.f / (1.f + expf(-zo));
            float cold = c_s[tid];
            float cn = fg * cold + ig * gg;
            float hn = og_ * tanhf(cn);
            bool mv = (tt < len_s[gb]);
            float hout = mv ? hn : h_s[gb*257 + hc];
            if (mv) c_s[tid] = cn;
            hsp[(size_t)(gb * T_ + tt) * H_ + hc] = hout;
            __threadfence();
        }
        __syncthreads();

        if (tid == 0) {
            atomicAdd((unsigned*)&g_bar[dir], 1u);
            unsigned target = (unsigned)(s + 1) * NC_DIR;
            while (*barp < target) __nanosleep(64);
            __threadfence();
        }
        __syncthreads();

        if (s < T_ - 1) {
            int lb = tid >> 3, kp = tid & 7;
            const float4* src = (const float4*)(hsp + (size_t)(lb * T_ + tt) * H_);
            float* dst = h_s + lb * 257;
#pragma unroll
            for (int ii = 0; ii < 8; ii++) {
                float4 v = src[ii * 8 + kp];
                int kb = ii * 32 + kp * 4;
                dst[kb + 0] = v.x; dst[kb + 1] = v.y;
                dst[kb + 2] = v.z; dst[kb + 3] = v.w;
            }
            __syncthreads();
        }
    }
}

// ---------------- kernel 3: dense projection to logits -----------------------
constexpr int DTOK = 16;
__global__ void __launch_bounds__(160)
bilstm_dense_kernel(const float* __restrict__ W, const float* __restrict__ bias,
                    float* __restrict__ out)
{
    __shared__ __align__(16) float hsm[DTOK * 513];
    const int tid = threadIdx.x;
    const int tok0 = blockIdx.x * DTOK;

    for (int idx = tid; idx < DTOK * 512; idx += 160) {
        int tk = idx >> 9, k = idx & 511;
        int tg = tok0 + tk;
        int b = tg >> 9, t = tg & 511;
        float v = (k < H_) ? g_hs[0][b][t][k] : g_hs[1][b][t][k - H_];
        hsm[tk * 513 + k] = v;
    }
    __syncthreads();

    if (tid < DTOK * C_) {
        int tk = tid / C_, c = tid % C_;
        float acc = bias[c];
        const float* hr = hsm + tk * 513;
#pragma unroll 8
        for (int k = 0; k < 512; k++) acc += hr[k] * W[k * C_ + c];
        out[(size_t)(tok0 + tk) * C_ + c] = acc;
    }
}

// ---------------- kernel 4: CRF log-likelihood + trans copy -----------------
__global__ void __launch_bounds__(32)
bilstm_crf_kernel(const float* __restrict__ logits,
                  const int* __restrict__ targets,
                  const int* __restrict__ lengths,
                  const float* __restrict__ trans,
                  float* __restrict__ out_ll, float* __restrict__ out_trans)
{
    __shared__ float tr[81];
    __shared__ float alpha[16];
    const int b = blockIdx.x;
    const int lane = threadIdx.x;

    for (int i = lane; i < 81; i += 32) tr[i] = trans[i];
    if (b == 0)
        for (int i = lane; i < 81; i += 32) out_trans[i] = trans[i];
    __syncwarp();

    const int len = lengths[b];
    const float* lg = logits + (size_t)b * T_ * C_;
    const int* tg = targets + b * T_;

    float us = 0.f, bs = 0.f;
    for (int t = lane; t < T_; t += 32) {
        if (t < len)     us += lg[t * C_ + tg[t]];
        if (t < len - 1) bs += tr[tg[t] * C_ + tg[t + 1]];
    }
#pragma unroll
    for (int off = 16; off; off >>= 1) {
        us += __shfl_xor_sync(0xffffffffu, us, off);
        bs += __shfl_xor_sync(0xffffffffu, bs, off);
    }

    if (lane < C_) alpha[lane] = lg[lane];
    __syncwarp();
    for (int t = 1; t < len; t++) {
        float a_new = 0.f;
        if (lane < C_) {
            float v[C_];
            float m = -1e30f;
#pragma unroll
            for (int c = 0; c < C_; c++) {
                v[c] = alpha[c] + tr[c * C_ + lane];
                m = fmaxf(m, v[c]);
            }
            float ssum = 0.f;
#pragma unroll
            for (int c = 0; c < C_; c++) ssum += expf(v[c] - m);
            a_new = m + logf(ssum) + lg[t * C_ + lane];
        }
        __syncwarp();
        if (lane < C_) alpha[lane] = a_new;
        __syncwarp();
    }

    if (lane == 0) {
        float m = -1e30f;
        for (int c = 0; c < C_; c++) m = fmaxf(m, alpha[c]);
        float ssum = 0.f;
        for (int c = 0; c < C_; c++) ssum += expf(alpha[c] - m);
        out_ll[b] = us + bs - (m + logf(ssum));
    }
}

// ---------------- launch ------------------------------------------------------
extern "C" void kernel_launch(void* const* d_in, const int* in_sizes, int n_in,
                              void* d_out, int out_size) {
    (void)in_sizes; (void)n_in; (void)out_size;
    const int*   inputs  = (const int*)  d_in[0];
    const int*   lengths = (const int*)  d_in[1];
    const int*   targets = (const int*)  d_in[2];
    const float* emb     = (const float*)d_in[3];
    const float* Wk_f    = (const float*)d_in[4];
    const float* Wr_f    = (const float*)d_in[5];
    const float* b_f     = (const float*)d_in[6];
    const float* Wk_b    = (const float*)d_in[7];
    const float* Wr_b    = (const float*)d_in[8];
    const float* b_b     = (const float*)d_in[9];
    const float* dW      = (const float*)d_in[10];
    const float* db      = (const float*)d_in[11];
    const float* trans   = (const float*)d_in[12];
    float* out = (float*)d_out;

    const int lstm_smem = (5120 + 16448 + 1088 + 256) * 4 + 64 * 4;  // 91904 B
    cudaFuncSetAttribute(bilstm_lstm_kernel,
                         cudaFuncAttributeMaxDynamicSharedMemorySize, lstm_smem);

    bilstm_init_kernel<<<1, 32>>>();

    dim3 gA(G_ / 64, NTOK / 64, 2);   // 16 x 512 x 2
    bilstm_xz_gemm_kernel<<<gA, 128>>>(inputs, lengths, emb, Wk_f, b_f, Wk_b, b_b);

    bilstm_lstm_kernel<<<2 * NC_DIR, RTHREADS, lstm_smem>>>(Wr_f, Wr_b, lengths);

    bilstm_dense_kernel<<<NTOK / DTOK, 160>>>(dW, db, out);

    bilstm_crf_kernel<<<B_, 32>>>(out, targets, lengths, trans,
                                  out + OFF_LL, out + OFF_TR);
}

// round 16
// speedup vs baseline: 1.6042x; 1.3771x over previous
#include <cuda_runtime.h>
#include <cstdint>
#include <cstddef>

// Problem constants
constexpr int B_  = 64;
constexpr int T_  = 512;
constexpr int D_  = 300;
constexpr int H_  = 256;
constexpr int G_  = 1024;   // 4*H
constexpr int C_  = 9;
constexpr int NTOK = B_ * T_;          // 32768
constexpr int NC_DIR = 64;             // CTAs per direction in recurrence
constexpr int RTHREADS = 512;

// Output layout: logits [B,T,C], log_likelihood [B], trans [C,C]
constexpr int OFF_LL = NTOK * C_;      // 294912
constexpr int OFF_TR = OFF_LL + B_;    // 294976

// smem strides (bank-conflict engineered)
constexpr int HS_STRIDE = 260;   // h_s: bank = (4g+q)%32 for mma a-frags -> conflict-free
constexpr int WR_STRIDE = 24;    // Wr_s: bank = (24q+g)%32 -> conflict-free
constexpr int ZP_STRIDE = 18;

// ---------------- scratch (device globals; no cudaMalloc allowed) -----------
__device__ float g_xz[2][NTOK][G_];          // emb@Wk + b, both dirs
__device__ float g_hs[2][B_][T_][H_];        // LSTM hidden outputs
__device__ unsigned g_bar[2];                // grid barrier counters

// ---------------- kernel 0: reset barrier counters --------------------------
__global__ void bilstm_init_kernel() {
    if (threadIdx.x < 2) g_bar[threadIdx.x] = 0u;
}

// ---------------- tf32 mma helpers ------------------------------------------
__device__ __forceinline__ unsigned f2tf(float f) {
    unsigned u;
    asm("cvt.rna.tf32.f32 %0, %1;" : "=r"(u) : "f"(f));
    return u;
}
__device__ __forceinline__ void mma_tf32(float c[4], const unsigned a[4], const unsigned b[2]) {
    asm volatile(
        "mma.sync.aligned.m16n8k8.row.col.f32.tf32.tf32.f32 "
        "{%0,%1,%2,%3}, {%4,%5,%6,%7}, {%8,%9}, {%0,%1,%2,%3};"
        : "+f"(c[0]), "+f"(c[1]), "+f"(c[2]), "+f"(c[3])
        : "r"(a[0]), "r"(a[1]), "r"(a[2]), "r"(a[3]), "r"(b[0]), "r"(b[1]));
}

// ---------------- kernel 1: fused embedding gather + input GEMM (tf32 HMMA) --
__global__ void __launch_bounds__(128)
bilstm_xz_gemm_kernel(const int* __restrict__ inputs,
                      const int* __restrict__ lengths,
                      const float* __restrict__ emb,
                      const float* __restrict__ Wk_f, const float* __restrict__ b_f,
                      const float* __restrict__ Wk_b, const float* __restrict__ b_b)
{
    __shared__ __align__(16) float As[64 * 20];
    __shared__ __align__(16) float Bs[16 * 72];

    const int m0 = blockIdx.y * 64;
    {   // skip tiles where every token is masked: values never used downstream
        const int bb = m0 >> 9;
        const int t0 = m0 & 511;
        if (t0 >= lengths[bb]) return;
    }

    const int dir = blockIdx.z;
    const float* Wk   = dir ? Wk_b : Wk_f;
    const float* bias = dir ? b_b  : b_f;
    const int n0 = blockIdx.x * 64;
    const int tid  = threadIdx.x;
    const int lane = tid & 31;
    const int wid  = tid >> 5;

    const int lm = tid >> 1, kq = (tid & 1) * 8;
    const int kr = tid >> 3, nq = (tid & 7) * 8;
    const int mw = (wid & 1) * 32, nw = (wid >> 1) * 32;
    const int g = lane >> 2, q = lane & 3;

    const int tok = inputs[m0 + lm];
    const float* arow = emb + (size_t)tok * D_;

    float acc[2][4][4];
#pragma unroll
    for (int mi = 0; mi < 2; mi++)
#pragma unroll
        for (int ni = 0; ni < 4; ni++)
#pragma unroll
            for (int e = 0; e < 4; e++) acc[mi][ni][e] = 0.f;

    for (int k0 = 0; k0 < 304; k0 += 16) {
        const bool full = (k0 + 16 <= D_);
        {
            float* dst = As + lm * 20 + kq;
            const int kk = k0 + kq;
            if (full) {
                *(float4*)(dst)     = *(const float4*)(arow + kk);
                *(float4*)(dst + 4) = *(const float4*)(arow + kk + 4);
            } else {
#pragma unroll
                for (int e = 0; e < 8; e++)
                    dst[e] = (kk + e < D_) ? arow[kk + e] : 0.f;
            }
        }
        {
            float* dst = Bs + kr * 72 + nq;
            const float* src = Wk + (size_t)(k0 + kr) * G_ + n0 + nq;
            if (full || (k0 + kr < D_)) {
                *(float4*)(dst)     = *(const float4*)(src);
                *(float4*)(dst + 4) = *(const float4*)(src + 4);
            } else {
                *(float4*)(dst)     = make_float4(0.f, 0.f, 0.f, 0.f);
                *(float4*)(dst + 4) = make_float4(0.f, 0.f, 0.f, 0.f);
            }
        }
        __syncthreads();

#pragma unroll
        for (int kb = 0; kb < 16; kb += 8) {
            unsigned af[2][4], bf[4][2];
#pragma unroll
            for (int mi = 0; mi < 2; mi++) {
                const float* ap = As + (mw + mi * 16 + g) * 20 + kb + q;
                af[mi][0] = f2tf(ap[0]);
                af[mi][1] = f2tf(ap[8 * 20]);
                af[mi][2] = f2tf(ap[4]);
                af[mi][3] = f2tf(ap[8 * 20 + 4]);
            }
#pragma unroll
            for (int ni = 0; ni < 4; ni++) {
                const float* bp = Bs + (kb + q) * 72 + nw + ni * 8 + g;
                bf[ni][0] = f2tf(bp[0]);
                bf[ni][1] = f2tf(bp[4 * 72]);
            }
#pragma unroll
            for (int mi = 0; mi < 2; mi++)
#pragma unroll
                for (int ni = 0; ni < 4; ni++)
                    mma_tf32(acc[mi][ni], af[mi], bf[ni]);
        }
        __syncthreads();
    }

    float* outp = &g_xz[dir][0][0];
#pragma unroll
    for (int mi = 0; mi < 2; mi++) {
        const int r = m0 + mw + mi * 16 + g;
#pragma unroll
        for (int ni = 0; ni < 4; ni++) {
            const int cc = n0 + nw + ni * 8 + q * 2;
            float2 bv = *(const float2*)(bias + cc);
            float2 o0, o1;
            o0.x = acc[mi][ni][0] + bv.x; o0.y = acc[mi][ni][1] + bv.y;
            o1.x = acc[mi][ni][2] + bv.x; o1.y = acc[mi][ni][3] + bv.y;
            *(float2*)(outp + (size_t)r * G_ + cc)       = o0;
            *(float2*)(outp + (size_t)(r + 8) * G_ + cc) = o1;
        }
    }
}

// ---------------- kernel 2: persistent bidirectional LSTM (tf32 HMMA GEMV) --
// 128 CTAs (0..63 fwd, 64..127 bwd), 512 threads. CTA (dir,j) owns hidden cols
// [4j,4j+4) = 16 gate cols. Per step: z = h_prev @ Wr_slice via 16 warps of
// m16n8k8 tf32 mma (8 output tiles x 2-way k-split), smem reduce, gates,
// hs store, release/acquire grid barrier, h reload.
__global__ void __launch_bounds__(RTHREADS, 1)
bilstm_lstm_kernel(const float* __restrict__ Wr_f,
                   const float* __restrict__ Wr_b,
                   const int* __restrict__ lengths)
{
    extern __shared__ __align__(16) float smem[];
    float* Wr_s = smem;                      // 256*24 = 6144
    float* h_s  = Wr_s + 6144;               // 64*260 = 16640
    float* zp   = h_s + 16640;               // 2*64*18 = 2304
    float* c_s  = zp + 2304;                 // 256
    int*   len_s = (int*)(c_s + 256);        // 64

    const int tid = threadIdx.x;
    const int dir = blockIdx.x >> 6;
    const int j   = blockIdx.x & 63;
    const float* Wr  = dir ? Wr_b : Wr_f;
    const float* xzp = &g_xz[dir][0][0];
    float* hsp = &g_hs[dir][0][0][0];

    // prologue
    for (int idx = tid; idx < 4096; idx += RTHREADS) {
        int k = idx >> 4, gi = idx & 15;
        int gate = gi >> 2, cc = gi & 3;
        Wr_s[k * WR_STRIDE + gi] = Wr[(size_t)k * G_ + gate * H_ + j*4 + cc];
    }
    for (int idx = tid; idx < 64 * HS_STRIDE; idx += RTHREADS) h_s[idx] = 0.f;
    if (tid < 256) c_s[tid] = 0.f;
    if (tid < 64)  len_s[tid] = lengths[tid];
    __syncthreads();

    // mma warp mapping: 16 warps = 4 m-tiles x 2 n-tiles x 2 k-halves
    const int wid = tid >> 5, lane = tid & 31;
    const int g = lane >> 2, q = lane & 3;
    const int m0w = (wid & 3) * 16;
    const int n0w = ((wid >> 2) & 1) * 8;
    const int kh  = wid >> 3;
    const float* aB = h_s + (m0w + g) * HS_STRIDE + kh * 128 + q;
    const float* bB = Wr_s + (kh * 128 + q) * WR_STRIDE + n0w + g;
    float* zpw = zp + kh * (64 * ZP_STRIDE) + n0w + 2 * q;

    // gate-phase mapping (tid < 256)
    const int gb = tid >> 2, gc = tid & 3;
    const int hc = j*4 + gc;

    unsigned* barp = &g_bar[dir];

    for (int s = 0; s < T_; s++) {
        const int tt = dir ? (T_ - 1 - s) : s;

        // prefetch xz for this step (DRAM latency hidden behind the mma loop)
        float xz0 = 0.f, xz1 = 0.f, xz2 = 0.f, xz3 = 0.f;
        if (tid < 256) {
            const float* xb = xzp + (size_t)(gb * T_ + tt) * G_ + hc;
            xz0 = xb[0]; xz1 = xb[H_]; xz2 = xb[2*H_]; xz3 = xb[3*H_];
        }

        // ---- z partial = h_prev @ Wr_slice  (16 tf32 mma per warp)
        float c[4] = {0.f, 0.f, 0.f, 0.f};
#pragma unroll
        for (int kk = 0; kk < 128; kk += 8) {
            unsigned af[4], bf[2];
            af[0] = f2tf(aB[kk]);
            af[1] = f2tf(aB[kk + 8 * HS_STRIDE]);
            af[2] = f2tf(aB[kk + 4]);
            af[3] = f2tf(aB[kk + 4 + 8 * HS_STRIDE]);
            bf[0] = f2tf(bB[kk * WR_STRIDE]);
            bf[1] = f2tf(bB[(kk + 4) * WR_STRIDE]);
            mma_tf32(c, af, bf);
        }
        *(float2*)(zpw + (m0w + g) * ZP_STRIDE)     = make_float2(c[0], c[1]);
        *(float2*)(zpw + (m0w + g + 8) * ZP_STRIDE) = make_float2(c[2], c[3]);
        __syncthreads();

        // ---- gate phase
        if (tid < 256) {
            const float* z0 = zp + gb * ZP_STRIDE;
            const float* z1 = z0 + 64 * ZP_STRIDE;
            float zi = z0[gc]      + z1[gc]      + xz0;
            float zf = z0[4 + gc]  + z1[4 + gc]  + xz1;
            float zg = z0[8 + gc]  + z1[8 + gc]  + xz2;
            float zo = z0[12 + gc] + z1[12 + gc] + xz3;
            float ig = 1.f / (1.f + expf(-zi));
            float fg = 1.f / (1.f + expf(-zf));
            float gg = tanhf(zg);
            float og_ = 1.f / (1.f + expf(-zo));
            float cold = c_s[tid];
            float cn = fg * cold + ig * gg;
            float hn = og_ * tanhf(cn);
            bool mv = (tt < len_s[gb]);
            float hout = mv ? hn : h_s[gb * HS_STRIDE + hc];
            if (mv) c_s[tid] = cn;
            hsp[(size_t)(gb * T_ + tt) * H_ + hc] = hout;
        }
        __syncthreads();

        // ---- release/acquire grid barrier for this direction
        if (tid == 0) {
            asm volatile("red.release.gpu.global.add.u32 [%0], %1;"
                         :: "l"(barp), "r"(1u) : "memory");
            const unsigned tgt = (unsigned)(s + 1) * NC_DIR;
            unsigned v;
            do {
                asm volatile("ld.acquire.gpu.global.u32 %0, [%1];"
                             : "=r"(v) : "l"(barp) : "memory");
            } while (v < tgt);
        }
        __syncthreads();

        // ---- reload h for next step
        if (s < T_ - 1) {
            int lb = tid >> 3, kp = tid & 7;
            const float4* src = (const float4*)(hsp + (size_t)(lb * T_ + tt) * H_);
            float* dst = h_s + lb * HS_STRIDE;
#pragma unroll
            for (int ii = 0; ii < 8; ii++) {
                float4 v = src[ii * 8 + kp];
                int kb = ii * 32 + kp * 4;
                dst[kb + 0] = v.x; dst[kb + 1] = v.y;
                dst[kb + 2] = v.z; dst[kb + 3] = v.w;
            }
            __syncthreads();
        }
    }
}

// ---------------- kernel 3: dense projection to logits -----------------------
constexpr int DTOK = 16;
__global__ void __launch_bounds__(160)
bilstm_dense_kernel(const float* __restrict__ W, const float* __restrict__ bias,
                    float* __restrict__ out)
{
    __shared__ __align__(16) float hsm[DTOK * 513];
    const int tid = threadIdx.x;
    const int tok0 = blockIdx.x * DTOK;

    for (int idx = tid; idx < DTOK * 512; idx += 160) {
        int tk = idx >> 9, k = idx & 511;
        int tg = tok0 + tk;
        int b = tg >> 9, t = tg & 511;
        float v = (k < H_) ? g_hs[0][b][t][k] : g_hs[1][b][t][k - H_];
        hsm[tk * 513 + k] = v;
    }
    __syncthreads();

    if (tid < DTOK * C_) {
        int tk = tid / C_, c = tid % C_;
        float acc = bias[c];
        const float* hr = hsm + tk * 513;
#pragma unroll 8
        for (int k = 0; k < 512; k++) acc += hr[k] * W[k * C_ + c];
        out[(size_t)(tok0 + tk) * C_ + c] = acc;
    }
}

// ---------------- kernel 4: CRF log-likelihood + trans copy -----------------
__global__ void __launch_bounds__(32)
bilstm_crf_kernel(const float* __restrict__ logits,
                  const int* __restrict__ targets,
                  const int* __restrict__ lengths,
                  const float* __restrict__ trans,
                  float* __restrict__ out_ll, float* __restrict__ out_trans)
{
    __shared__ float tr[81];
    __shared__ float alpha[16];
    const int b = blockIdx.x;
    const int lane = threadIdx.x;

    for (int i = lane; i < 81; i += 32) tr[i] = trans[i];
    if (b == 0)
        for (int i = lane; i < 81; i += 32) out_trans[i] = trans[i];
    __syncwarp();

    const int len = lengths[b];
    const float* lg = logits + (size_t)b * T_ * C_;
    const int* tg = targets + b * T_;

    float us = 0.f, bs = 0.f;
    for (int t = lane; t < T_; t += 32) {
        if (t < len)     us += lg[t * C_ + tg[t]];
        if (t < len - 1) bs += tr[tg[t] * C_ + tg[t + 1]];
    }
#pragma unroll
    for (int off = 16; off; off >>= 1) {
        us += __shfl_xor_sync(0xffffffffu, us, off);
        bs += __shfl_xor_sync(0xffffffffu, bs, off);
    }

    if (lane < C_) alpha[lane] = lg[lane];
    __syncwarp();
    for (int t = 1; t < len; t++) {
        float a_new = 0.f;
        if (lane < C_) {
            float v[C_];
            float m = -1e30f;
#pragma unroll
            for (int c = 0; c < C_; c++) {
                v[c] = alpha[c] + tr[c * C_ + lane];
                m = fmaxf(m, v[c]);
            }
            float ssum = 0.f;
#pragma unroll
            for (int c = 0; c < C_; c++) ssum += expf(v[c] - m);
            a_new = m + logf(ssum) + lg[t * C_ + lane];
        }
        __syncwarp();
        if (lane < C_) alpha[lane] = a_new;
        __syncwarp();
    }

    if (lane == 0) {
        float m = -1e30f;
        for (int c = 0; c < C_; c++) m = fmaxf(m, alpha[c]);
        float ssum = 0.f;
        for (int c = 0; c < C_; c++) ssum += expf(alpha[c] - m);
        out_ll[b] = us + bs - (m + logf(ssum));
    }
}

// ---------------- launch ------------------------------------------------------
extern "C" void kernel_launch(void* const* d_in, const int* in_sizes, int n_in,
                              void* d_out, int out_size) {
    (void)in_sizes; (void)n_in; (void)out_size;
    const int*   inputs  = (const int*)  d_in[0];
    const int*   lengths = (const int*)  d_in[1];
    const int*   targets = (const int*)  d_in[2];
    const float* emb     = (const float*)d_in[3];
    const float* Wk_f    = (const float*)d_in[4];
    const float* Wr_f    = (const float*)d_in[5];
    const float* b_f     = (const float*)d_in[6];
    const float* Wk_b    = (const float*)d_in[7];
    const float* Wr_b    = (const float*)d_in[8];
    const float* b_b     = (const float*)d_in[9];
    const float* dW      = (const float*)d_in[10];
    const float* db      = (const float*)d_in[11];
    const float* trans   = (const float*)d_in[12];
    float* out = (float*)d_out;

    const int lstm_smem = (6144 + 16640 + 2304 + 256) * 4 + 64 * 4;  // 101632 B
    cudaFuncSetAttribute(bilstm_lstm_kernel,
                         cudaFuncAttributeMaxDynamicSharedMemorySize, lstm_smem);

    bilstm_init_kernel<<<1, 32>>>();

    dim3 gA(G_ / 64, NTOK / 64, 2);
    bilstm_xz_gemm_kernel<<<gA, 128>>>(inputs, lengths, emb, Wk_f, b_f, Wk_b, b_b);

    bilstm_lstm_kernel<<<2 * NC_DIR, RTHREADS, lstm_smem>>>(Wr_f, Wr_b, lengths);

    bilstm_dense_kernel<<<NTOK / DTOK, 160>>>(dW, db, out);

    bilstm_crf_kernel<<<B_, 32>>>(out, targets, lengths, trans,
                                  out + OFF_LL, out + OFF_TR);
}